// round 2
// baseline (speedup 1.0000x reference)
#include <cuda_runtime.h>
#include <cstdint>

#define DMODEL 256
#define D4     64
#define MAXN   100000
#define MAXE   1700000

// ---------------- scratch (static device globals) ----------------------------
__device__ float    g_h0[(size_t)MAXN * 256];
__device__ float    g_h1[(size_t)MAXN * 512];
__device__ uint32_t g_Bt1[256 * 512];          // W1 tf32, tiled/permuted
__device__ uint32_t g_Bt2[512 * 256];          // W2 tf32, tiled/permuted
__device__ int      g_deg[MAXN];
__device__ int      g_rowptr[MAXN];
__device__ int      g_cursor[MAXN];
__device__ int      g_esrc[MAXE];
__device__ int      g_bsum[512];
__device__ float    g_colsum[256];
__device__ float    g_colsq[256];
__device__ float    g_scale[256];
__device__ float    g_shift[256];
__device__ int      g_idx64;

// ---------------- helpers ----------------------------------------------------
__device__ __forceinline__ uint32_t f2tf(float f) {
    uint32_t r;
    asm("cvt.rna.tf32.f32 %0, %1;" : "=r"(r) : "f"(f));
    return r;
}

__device__ __forceinline__ void mma_tf32(float* c, const uint32_t* a, const uint32_t* b) {
    asm volatile(
        "mma.sync.aligned.m16n8k8.row.col.f32.tf32.tf32.f32 "
        "{%0,%1,%2,%3}, {%4,%5,%6,%7}, {%8,%9}, {%0,%1,%2,%3};"
        : "+f"(c[0]), "+f"(c[1]), "+f"(c[2]), "+f"(c[3])
        : "r"(a[0]), "r"(a[1]), "r"(a[2]), "r"(a[3]), "r"(b[0]), "r"(b[1]));
}

// ---------------- prolog: zero deg + BN accumulators + sniff index dtype -----
__global__ void k_prolog(const void* __restrict__ idxbuf, int n) {
    for (int i = blockIdx.x * blockDim.x + threadIdx.x; i < n; i += gridDim.x * blockDim.x)
        g_deg[i] = 0;
    if (blockIdx.x == 0) {
        int t = threadIdx.x;
        if (t < 256) { g_colsum[t] = 0.f; g_colsq[t] = 0.f; }
        if (t == 0) {
            const unsigned long long* p = (const unsigned long long*)idxbuf;
            int is64 = 1;
            #pragma unroll 1
            for (int i = 0; i < 64; i++) {
                if ((p[i] >> 32) != 0ull) { is64 = 0; break; }
            }
            g_idx64 = is64;
        }
    }
}

// ---------------- weight pre-transform: fp32 [K,NT] -> tf32 tiled/permuted ---
// out[((bn*(KK/32)+kt))*2048 + c*32 + slot], slot pairs (k, k+4) adjacent.
__global__ void k_prepB(const float* __restrict__ W, uint32_t* __restrict__ out,
                        int total, int lgNT, int ktw) {
    for (int i = blockIdx.x * blockDim.x + threadIdx.x; i < total; i += gridDim.x * blockDim.x) {
        int col = i & ((1 << lgNT) - 1);
        int k   = i >> lgNT;
        int bn = col >> 6, c = col & 63;
        int kt = k >> 5, kl = k & 31;
        int slot = ((kl >> 3) << 3) + ((kl & 3) << 1) + ((kl >> 2) & 1);
        out[(((bn * ktw + kt) << 11)) + (c << 5) + slot] = f2tf(W[i]);
    }
}

// ---------------- CSR build --------------------------------------------------
__global__ void k_hist(const void* __restrict__ dstb, int E) {
    int e = blockIdx.x * blockDim.x + threadIdx.x;
    if (e >= E) return;
    int d = g_idx64 ? (int)((const long long*)dstb)[e] : ((const int*)dstb)[e];
    atomicAdd(&g_deg[d], 1);
}

__global__ void k_chunksum(int n) {
    __shared__ int sm[512];
    int t = threadIdx.x;
    int i = blockIdx.x * 512 + t;
    sm[t] = (i < n) ? g_deg[i] : 0;
    __syncthreads();
    for (int off = 256; off > 0; off >>= 1) {
        if (t < off) sm[t] += sm[t + off];
        __syncthreads();
    }
    if (t == 0) g_bsum[blockIdx.x] = sm[0];
}

__global__ void k_scanbsum(int nb) {
    if (threadIdx.x == 0) {
        int run = 0;
        for (int b = 0; b < nb; b++) { int v = g_bsum[b]; g_bsum[b] = run; run += v; }
    }
}

__global__ void k_scanwrite(int n) {
    __shared__ int sm[512];
    int t = threadIdx.x;
    int i = blockIdx.x * 512 + t;
    int v = (i < n) ? g_deg[i] : 0;
    sm[t] = v;
    __syncthreads();
    for (int off = 1; off < 512; off <<= 1) {
        int x = (t >= off) ? sm[t - off] : 0;
        __syncthreads();
        sm[t] += x;
        __syncthreads();
    }
    if (i < n) {
        int excl = g_bsum[blockIdx.x] + sm[t] - v;
        g_rowptr[i] = excl;
        g_cursor[i] = excl;
    }
}

__global__ void k_reorder(const void* __restrict__ srcb, const void* __restrict__ dstb, int E) {
    int e = blockIdx.x * blockDim.x + threadIdx.x;
    if (e >= E) return;
    int s, d;
    if (g_idx64) {
        s = (int)((const long long*)srcb)[e];
        d = (int)((const long long*)dstb)[e];
    } else {
        s = ((const int*)srcb)[e];
        d = ((const int*)dstb)[e];
    }
    int pos = atomicAdd(&g_cursor[d], 1);
    g_esrc[pos] = s;
}

// ---------------- gather-sum per node (one warp), fused with (1+eps)*x ------
__global__ void k_gather(const float4* __restrict__ x, const float* __restrict__ eps, int n) {
    int w    = (int)((blockIdx.x * blockDim.x + threadIdx.x) >> 5);
    int lane = threadIdx.x & 31;
    if (w >= n) return;
    int start = g_rowptr[w], deg = g_deg[w];
    float4 a0 = make_float4(0.f, 0.f, 0.f, 0.f);
    float4 a1 = make_float4(0.f, 0.f, 0.f, 0.f);
    int i = 0;
    for (; i + 2 <= deg; i += 2) {
        int s0 = __ldg(&g_esrc[start + i]);
        int s1 = __ldg(&g_esrc[start + i + 1]);
        const float4* p0 = x + (size_t)s0 * D4;
        const float4* p1 = x + (size_t)s1 * D4;
        float4 v00 = __ldg(p0 + lane), v01 = __ldg(p0 + lane + 32);
        float4 v10 = __ldg(p1 + lane), v11 = __ldg(p1 + lane + 32);
        a0.x += v00.x + v10.x; a0.y += v00.y + v10.y;
        a0.z += v00.z + v10.z; a0.w += v00.w + v10.w;
        a1.x += v01.x + v11.x; a1.y += v01.y + v11.y;
        a1.z += v01.z + v11.z; a1.w += v01.w + v11.w;
    }
    if (i < deg) {
        int s0 = __ldg(&g_esrc[start + i]);
        const float4* p0 = x + (size_t)s0 * D4;
        float4 v00 = __ldg(p0 + lane), v01 = __ldg(p0 + lane + 32);
        a0.x += v00.x; a0.y += v00.y; a0.z += v00.z; a0.w += v00.w;
        a1.x += v01.x; a1.y += v01.y; a1.z += v01.z; a1.w += v01.w;
    }
    float s = 1.0f + __ldg(eps);
    const float4* px = x + (size_t)w * D4;
    float4 x0 = __ldg(px + lane), x1 = __ldg(px + lane + 32);
    float4* o = (float4*)g_h0 + (size_t)w * D4;
    o[lane]      = make_float4(fmaf(s, x0.x, a0.x), fmaf(s, x0.y, a0.y),
                               fmaf(s, x0.z, a0.z), fmaf(s, x0.w, a0.w));
    o[lane + 32] = make_float4(fmaf(s, x1.x, a1.x), fmaf(s, x1.y, a1.y),
                               fmaf(s, x1.z, a1.z), fmaf(s, x1.w, a1.w));
}

// ---------------- tf32 tensor-core GEMM:  C[M,NT] = A[M,K] @ B[K,NT] + bias --
// 128x64 block tile, BK=32, 8 warps (4x2), LDS.64 fragment loads (stride 40),
// register double-buffered k-tiles. B comes pre-converted/permuted (g_Bt*).
template <int K, int NT, bool RELU, bool STATS>
__global__ __launch_bounds__(256, 2)
void k_gemm(const float* __restrict__ A, const uint32_t* __restrict__ Bt,
            const float* __restrict__ bias, float* __restrict__ C, int M) {
    constexpr int KT = K / 32;
    __shared__ __align__(16) uint32_t As[128 * 40];
    __shared__ __align__(16) uint32_t Bs[64 * 40];
    __shared__ float s_sum[64];
    __shared__ float s_sq[64];

    const int tid  = threadIdx.x;
    const int warp = tid >> 5, lane = tid & 31;
    const int wm = warp >> 1, wn = warp & 1;
    const int gid = lane >> 2, tig = lane & 3;
    const int bm = blockIdx.y, bn = blockIdx.x;
    const int row0 = bm * 128;

    float acc[2][4][4];
    #pragma unroll
    for (int i = 0; i < 2; i++)
        #pragma unroll
        for (int j = 0; j < 4; j++)
            #pragma unroll
            for (int l = 0; l < 4; l++) acc[i][j][l] = 0.f;

    float4 rA[2][2];
    uint4  rB[2];

    auto loadA = [&](int kt) {
        #pragma unroll
        for (int j = 0; j < 2; j++) {
            int u = tid + j * 256;
            int r = u & 127, kg = u >> 7;
            int grow = row0 + r;
            if (grow < M) {
                const float* p = A + (size_t)grow * K + kt * 32 + kg * 8;
                rA[j][0] = *(const float4*)p;
                rA[j][1] = *(const float4*)(p + 4);
            } else {
                rA[j][0] = make_float4(0.f, 0.f, 0.f, 0.f);
                rA[j][1] = make_float4(0.f, 0.f, 0.f, 0.f);
            }
        }
    };
    auto loadB = [&](int kt) {
        const uint4* chunk = (const uint4*)(Bt + ((size_t)(bn * KT + kt) << 11));
        #pragma unroll
        for (int j = 0; j < 2; j++) rB[j] = chunk[tid + j * 256];
    };
    auto storeAB = [&]() {
        #pragma unroll
        for (int j = 0; j < 2; j++) {
            int u = tid + j * 256;
            int r = u & 127, kg = u >> 7;
            float4 va = rA[j][0], vb = rA[j][1];
            uint4 w0 = make_uint4(f2tf(va.x), f2tf(vb.x), f2tf(va.y), f2tf(vb.y));
            uint4 w1 = make_uint4(f2tf(va.z), f2tf(vb.z), f2tf(va.w), f2tf(vb.w));
            *(uint4*)&As[r * 40 + kg * 8]     = w0;
            *(uint4*)&As[r * 40 + kg * 8 + 4] = w1;
        }
        #pragma unroll
        for (int j = 0; j < 2; j++) {
            int idx4 = tid + j * 256;
            int c = idx4 >> 3, q = idx4 & 7;
            *(uint4*)&Bs[c * 40 + q * 4] = rB[j];
        }
    };

    loadA(0); loadB(0);

    for (int kt = 0; kt < KT; ++kt) {
        if (kt) __syncthreads();
        storeAB();
        __syncthreads();
        if (kt + 1 < KT) { loadA(kt + 1); loadB(kt + 1); }

        #pragma unroll
        for (int kk = 0; kk < 4; kk++) {
            uint32_t a[2][4], b[4][2];
            #pragma unroll
            for (int mf = 0; mf < 2; mf++) {
                int base = (wm * 32 + mf * 16 + gid) * 40 + kk * 8 + 2 * tig;
                uint2 lo = *(const uint2*)&As[base];
                uint2 hi = *(const uint2*)&As[base + 8 * 40];
                a[mf][0] = lo.x; a[mf][2] = lo.y;
                a[mf][1] = hi.x; a[mf][3] = hi.y;
            }
            #pragma unroll
            for (int nf = 0; nf < 4; nf++) {
                int col = wn * 32 + nf * 8 + gid;
                uint2 bb = *(const uint2*)&Bs[col * 40 + kk * 8 + 2 * tig];
                b[nf][0] = bb.x; b[nf][1] = bb.y;
            }
            #pragma unroll
            for (int mf = 0; mf < 2; mf++)
                #pragma unroll
                for (int nf = 0; nf < 4; nf++)
                    mma_tf32(acc[mf][nf], a[mf], b[nf]);
        }
    }

    // -------- epilogue: bias (+relu) (+BN stats) --------
    float lsum[8], lsq[8];
    #pragma unroll
    for (int i = 0; i < 8; i++) { lsum[i] = 0.f; lsq[i] = 0.f; }

    #pragma unroll
    for (int mf = 0; mf < 2; mf++) {
        #pragma unroll
        for (int h = 0; h < 2; h++) {
            int row = row0 + wm * 32 + mf * 16 + gid + h * 8;
            bool ok = row < M;
            #pragma unroll
            for (int nf = 0; nf < 4; nf++) {
                int col = bn * 64 + wn * 32 + nf * 8 + 2 * tig;
                float v0 = acc[mf][nf][2 * h + 0] + __ldg(&bias[col]);
                float v1 = acc[mf][nf][2 * h + 1] + __ldg(&bias[col + 1]);
                if (RELU) { v0 = fmaxf(v0, 0.f); v1 = fmaxf(v1, 0.f); }
                if (ok) {
                    *(float2*)(C + (size_t)row * NT + col) = make_float2(v0, v1);
                    if (STATS) {
                        lsum[nf * 2    ] += v0; lsq[nf * 2    ] += v0 * v0;
                        lsum[nf * 2 + 1] += v1; lsq[nf * 2 + 1] += v1 * v1;
                    }
                }
            }
        }
    }

    if (STATS) {
        if (tid < 64) { s_sum[tid] = 0.f; s_sq[tid] = 0.f; }
        __syncthreads();
        #pragma unroll
        for (int nf = 0; nf < 4; nf++)
            #pragma unroll
            for (int j = 0; j < 2; j++) {
                int lc = wn * 32 + nf * 8 + 2 * tig + j;
                atomicAdd(&s_sum[lc], lsum[nf * 2 + j]);
                atomicAdd(&s_sq[lc],  lsq[nf * 2 + j]);
            }
        __syncthreads();
        if (tid < 64) {
            atomicAdd(&g_colsum[bn * 64 + tid], s_sum[tid]);
            atomicAdd(&g_colsq[bn * 64 + tid],  s_sq[tid]);
        }
    }
}

// ---------------- BN finalize + apply ---------------------------------------
__global__ void k_finalize(const float* __restrict__ gamma,
                           const float* __restrict__ beta, float invN) {
    int c = threadIdx.x;
    float mean = g_colsum[c] * invN;
    float var  = g_colsq[c] * invN - mean * mean;
    var = fmaxf(var, 0.f);
    float inv  = rsqrtf(var + 1e-5f);
    float sc   = gamma[c] * inv;
    g_scale[c] = sc;
    g_shift[c] = beta[c] - mean * sc;
}

__global__ void k_bn(float4* __restrict__ out, int n4) {
    const float4* sc4 = (const float4*)g_scale;
    const float4* sh4 = (const float4*)g_shift;
    for (int i = blockIdx.x * blockDim.x + threadIdx.x; i < n4; i += gridDim.x * blockDim.x) {
        int c4 = i & (D4 - 1);
        float4 sc = sc4[c4], sh = sh4[c4];
        float4 v = out[i];
        v.x = fmaf(v.x, sc.x, sh.x);
        v.y = fmaf(v.y, sc.y, sh.y);
        v.z = fmaf(v.z, sc.z, sh.z);
        v.w = fmaf(v.w, sc.w, sh.w);
        out[i] = v;
    }
}

// ---------------- launch -----------------------------------------------------
extern "C" void kernel_launch(void* const* d_in, const int* in_sizes, int n_in,
                              void* d_out, int out_size) {
    const float* x     = (const float*)d_in[0];
    const void*  src   = d_in[1];
    const void*  dst   = d_in[2];
    const float* eps   = (const float*)d_in[3];
    const float* W1    = (const float*)d_in[4];
    const float* b1    = (const float*)d_in[5];
    const float* W2    = (const float*)d_in[6];
    const float* b2    = (const float*)d_in[7];
    const float* gamma = (const float*)d_in[8];
    const float* beta  = (const float*)d_in[9];
    float* out = (float*)d_out;

    int M  = in_sizes[0] / DMODEL;
    int E  = in_sizes[1];
    int n4 = M * D4;

    void* ph0  = nullptr; cudaGetSymbolAddress(&ph0,  g_h0);
    void* ph1  = nullptr; cudaGetSymbolAddress(&ph1,  g_h1);
    void* pbt1 = nullptr; cudaGetSymbolAddress(&pbt1, g_Bt1);
    void* pbt2 = nullptr; cudaGetSymbolAddress(&pbt2, g_Bt2);

    int NSB = (M + 511) / 512;

    k_prolog<<<128, 256>>>(src, M);
    k_prepB<<<256, 256>>>(W1, (uint32_t*)pbt1, 256 * 512, 9, 8);
    k_prepB<<<256, 256>>>(W2, (uint32_t*)pbt2, 512 * 256, 8, 16);
    k_hist<<<(E + 255) / 256, 256>>>(dst, E);
    k_chunksum<<<NSB, 512>>>(M);
    k_scanbsum<<<1, 32>>>(NSB);
    k_scanwrite<<<NSB, 512>>>(M);
    k_reorder<<<(E + 255) / 256, 256>>>(src, dst, E);
    k_gather<<<(M * 32 + 255) / 256, 256>>>((const float4*)x, eps, M);

    int mt = (M + 127) / 128;
    k_gemm<256, 512, true,  false><<<dim3(8, mt), 256>>>((const float*)ph0, (const uint32_t*)pbt1, b1, (float*)ph1, M);
    k_gemm<512, 256, false, true ><<<dim3(4, mt), 256>>>((const float*)ph1, (const uint32_t*)pbt2, b2, out, M);

    k_finalize<<<1, 256>>>(gamma, beta, 1.0f / (float)M);
    k_bn<<<2048, 256>>>((float4*)out, n4);
}